// round 2
// baseline (speedup 1.0000x reference)
#include <cuda_runtime.h>
#include <cstdint>

#define NNZ_C   1600000
#define NE_C    100000
#define KTOP_C  50000
#define D_C     128
#define H_C     32

// ---------------- device scratch (no allocations allowed) ----------------
__device__ int            g_counts[NE_C];
__device__ int            g_offsets[NE_C + 1];
__device__ int            g_cursor[NE_C];
__device__ int            g_csr_v[NNZ_C];
__device__ unsigned       g_keys[NE_C];
__device__ unsigned       g_hist1[65536];
__device__ unsigned       g_hist2[65536];
__device__ unsigned       g_selHi;
__device__ unsigned       g_remK;
__device__ unsigned       g_thresh;
__device__ unsigned       g_rneed;
__device__ unsigned char  g_keep[NE_C];

// ---------------- init: zero the per-launch state ----------------
__global__ void __launch_bounds__(256) k_init() {
    int i = blockIdx.x * blockDim.x + threadIdx.x;
    int stride = gridDim.x * blockDim.x;
    for (int j = i; j < NE_C; j += stride) { g_counts[j] = 0; g_cursor[j] = 0; }
    for (int j = i; j < 65536; j += stride) { g_hist1[j] = 0; g_hist2[j] = 0; }
}

// ---------------- pass A: degree counts ----------------
__global__ void __launch_bounds__(256) k_count(const int* __restrict__ E_idx) {
    int i0 = blockIdx.x * blockDim.x + threadIdx.x;
    int stride = gridDim.x * blockDim.x;
    for (int i = i0; i < NNZ_C; i += stride)
        atomicAdd(&g_counts[E_idx[i]], 1);
}

// ---------------- pass B: exclusive scan of counts (single block) ----------------
__global__ void __launch_bounds__(1024) k_scan() {
    __shared__ int ssum[1024];
    const int CH = (NE_C + 1023) / 1024;   // 98
    int t = threadIdx.x;
    int base = t * CH;
    int s = 0;
    for (int i = 0; i < CH; i++) {
        int idx = base + i;
        if (idx < NE_C) s += g_counts[idx];
    }
    ssum[t] = s;
    __syncthreads();
    for (int off = 1; off < 1024; off <<= 1) {
        int v = (t >= off) ? ssum[t - off] : 0;
        __syncthreads();
        ssum[t] += v;
        __syncthreads();
    }
    int run = (t > 0) ? ssum[t - 1] : 0;
    for (int i = 0; i < CH; i++) {
        int idx = base + i;
        if (idx < NE_C) {
            g_offsets[idx] = run;
            run += g_counts[idx];
        }
    }
    if (t == 1023) g_offsets[NE_C] = ssum[1023];
}

// ---------------- pass C: scatter V_idx into CSR order ----------------
__global__ void __launch_bounds__(256) k_scatter(const int* __restrict__ V_idx,
                                                 const int* __restrict__ E_idx) {
    int i0 = blockIdx.x * blockDim.x + threadIdx.x;
    int stride = gridDim.x * blockDim.x;
    for (int i = i0; i < NNZ_C; i += stride) {
        int e = E_idx[i];
        int p = atomicAdd(&g_cursor[e], 1);
        g_csr_v[g_offsets[e] + p] = V_idx[i];
    }
}

// ---------------- fused edge-feature mean + MLP + sigmoid ----------------
// One warp per edge. Lane l accumulates features [4l..4l+3] in a float4.
// MLP: lane j computes h_j = relu(sum_d f[d]*W1[d][j] + b1[j]); warp-reduce h.W2.
__global__ void __launch_bounds__(256) k_edge(
    const float* __restrict__ X,
    const float* __restrict__ W1,
    const float* __restrict__ b1,
    const float* __restrict__ W2,
    const float* __restrict__ b2,
    float* __restrict__ probs_out)
{
    __shared__ float  sW1[D_C * H_C];     // 16 KB, [d*32 + j]
    __shared__ float  sb1[H_C];
    __shared__ float  sW2[H_C];
    __shared__ float  sB2;
    __shared__ float4 sfeat[8][32];       // 4 KB, per-warp feature vector

    int tid = threadIdx.x;
    for (int i = tid; i < D_C * H_C; i += blockDim.x) sW1[i] = W1[i];
    if (tid < H_C) { sb1[tid] = b1[tid]; sW2[tid] = W2[tid]; }
    if (tid == 0) sB2 = b2[0];
    __syncthreads();

    int warp = tid >> 5;
    int lane = tid & 31;

    for (int e = blockIdx.x * 8 + warp; e < NE_C; e += gridDim.x * 8) {
        int s   = g_offsets[e];
        int deg = g_offsets[e + 1] - s;

        float4 acc = make_float4(0.f, 0.f, 0.f, 0.f);
        for (int base = 0; base < deg; base += 32) {
            int n = min(32, deg - base);
            int v = (lane < n) ? g_csr_v[s + base + lane] : 0;
            #pragma unroll 4
            for (int m = 0; m < n; m++) {
                int vm = __shfl_sync(0xffffffffu, v, m);
                float4 x = __ldg(((const float4*)(X + (size_t)vm * D_C)) + lane);
                acc.x += x.x; acc.y += x.y; acc.z += x.z; acc.w += x.w;
            }
        }
        float inv = (deg > 0) ? (1.0f / (float)deg) : 0.0f;
        acc.x *= inv; acc.y *= inv; acc.z *= inv; acc.w *= inv;

        sfeat[warp][lane] = acc;
        __syncwarp();

        // lane j computes h_j
        const float4* f4 = sfeat[warp];
        float h = sb1[lane];
        #pragma unroll
        for (int d4 = 0; d4 < 32; d4++) {
            float4 fv = f4[d4];
            h += fv.x * sW1[(d4 * 4 + 0) * H_C + lane];
            h += fv.y * sW1[(d4 * 4 + 1) * H_C + lane];
            h += fv.z * sW1[(d4 * 4 + 2) * H_C + lane];
            h += fv.w * sW1[(d4 * 4 + 3) * H_C + lane];
        }
        float contrib = fmaxf(h, 0.0f) * sW2[lane];
        #pragma unroll
        for (int off = 16; off > 0; off >>= 1)
            contrib += __shfl_xor_sync(0xffffffffu, contrib, off);

        if (lane == 0) {
            float logit = contrib + sB2;
            float prob  = 1.0f / (1.0f + expf(-logit));
            probs_out[e] = prob;
            g_keys[e]    = __float_as_uint(prob);  // probs > 0 => monotone as uint
        }
        __syncwarp();
    }
}

// ---------------- radix select (2 x 16-bit) ----------------
__global__ void __launch_bounds__(256) k_hist1() {
    int i0 = blockIdx.x * blockDim.x + threadIdx.x;
    int stride = gridDim.x * blockDim.x;
    for (int i = i0; i < NE_C; i += stride)
        atomicAdd(&g_hist1[g_keys[i] >> 16], 1u);
}

__global__ void __launch_bounds__(1024) k_select1() {
    __shared__ unsigned ssum[1024];
    const int CH = 64;
    int t = threadIdx.x;
    unsigned s = 0;
    for (int i = 0; i < CH; i++) {
        int bin = 65535 - (t * CH + i);    // descending key order
        s += g_hist1[bin];
    }
    ssum[t] = s;
    __syncthreads();
    for (int off = 1; off < 1024; off <<= 1) {
        unsigned v = (t >= off) ? ssum[t - off] : 0;
        __syncthreads();
        ssum[t] += v;
        __syncthreads();
    }
    unsigned run = (t > 0) ? ssum[t - 1] : 0;
    for (int i = 0; i < CH; i++) {
        int bin = 65535 - (t * CH + i);
        unsigned c = g_hist1[bin];
        if (run < KTOP_C && KTOP_C <= run + c) {
            g_selHi = (unsigned)bin;
            g_remK  = KTOP_C - run;
        }
        run += c;
    }
}

__global__ void __launch_bounds__(256) k_hist2() {
    int i0 = blockIdx.x * blockDim.x + threadIdx.x;
    int stride = gridDim.x * blockDim.x;
    unsigned hi = g_selHi;
    for (int i = i0; i < NE_C; i += stride) {
        unsigned k = g_keys[i];
        if ((k >> 16) == hi) atomicAdd(&g_hist2[k & 0xffffu], 1u);
    }
}

__global__ void __launch_bounds__(1024) k_select2() {
    __shared__ unsigned ssum[1024];
    const int CH = 64;
    int t = threadIdx.x;
    unsigned K = g_remK;
    unsigned s = 0;
    for (int i = 0; i < CH; i++) {
        int bin = 65535 - (t * CH + i);
        s += g_hist2[bin];
    }
    ssum[t] = s;
    __syncthreads();
    for (int off = 1; off < 1024; off <<= 1) {
        unsigned v = (t >= off) ? ssum[t - off] : 0;
        __syncthreads();
        ssum[t] += v;
        __syncthreads();
    }
    unsigned run = (t > 0) ? ssum[t - 1] : 0;
    for (int i = 0; i < CH; i++) {
        int bin = 65535 - (t * CH + i);
        unsigned c = g_hist2[bin];
        if (run < K && K <= run + c) {
            g_thresh = (g_selHi << 16) | (unsigned)bin;
            g_rneed  = K - run;        // how many of the ==threshold keys to keep
        }
        run += c;
    }
}

// deterministic index-order tie-break for keys == threshold (single block)
__global__ void __launch_bounds__(1024) k_mark_keep() {
    __shared__ int ssum[1024];
    const int CH = (NE_C + 1023) / 1024;   // 98
    int t = threadIdx.x;
    unsigned T = g_thresh;
    unsigned r = g_rneed;
    int base = t * CH;
    int eq = 0;
    for (int i = 0; i < CH; i++) {
        int idx = base + i;
        if (idx < NE_C && g_keys[idx] == T) eq++;
    }
    ssum[t] = eq;
    __syncthreads();
    for (int off = 1; off < 1024; off <<= 1) {
        int v = (t >= off) ? ssum[t - off] : 0;
        __syncthreads();
        ssum[t] += v;
        __syncthreads();
    }
    int rank = (t > 0) ? ssum[t - 1] : 0;
    for (int i = 0; i < CH; i++) {
        int idx = base + i;
        if (idx < NE_C) {
            unsigned k = g_keys[idx];
            unsigned char kp;
            if (k > T)      kp = 1;
            else if (k == T) { kp = (rank < (int)r) ? 1 : 0; rank++; }
            else            kp = 0;
            g_keep[idx] = kp;
        }
    }
}

// ---------------- final output: stacked (2 x NNZ) + mask (NNZ) as float32 ----------------
__global__ void __launch_bounds__(256) k_final(const int* __restrict__ V_idx,
                                               const int* __restrict__ E_idx,
                                               float* __restrict__ out)
{
    int i = blockIdx.x * blockDim.x + threadIdx.x;
    if (i >= NNZ_C) return;
    int v = V_idx[i];
    int e = E_idx[i];
    bool m = (g_keep[e] != 0);
    out[i]                     = m ? (float)v : -1.0f;
    out[NNZ_C + i]             = m ? (float)e : -1.0f;
    out[2 * NNZ_C + NE_C + i]  = m ? 1.0f : 0.0f;
}

// ---------------- launch ----------------
extern "C" void kernel_launch(void* const* d_in, const int* in_sizes, int n_in,
                              void* d_out, int out_size)
{
    const float* X     = (const float*)d_in[0];
    const int*   V_idx = (const int*)  d_in[1];
    const int*   E_idx = (const int*)  d_in[2];
    const float* W1    = (const float*)d_in[3];
    const float* b1    = (const float*)d_in[4];
    const float* W2    = (const float*)d_in[5];
    const float* b2    = (const float*)d_in[6];
    float* out = (float*)d_out;
    float* probs_out = out + 2 * NNZ_C;   // probs region of the concatenated output

    k_init    <<<256, 256>>>();
    k_count   <<<1024, 256>>>(E_idx);
    k_scan    <<<1, 1024>>>();
    k_scatter <<<1024, 256>>>(V_idx, E_idx);
    k_edge    <<<1184, 256>>>(X, W1, b1, W2, b2, probs_out);
    k_hist1   <<<391, 256>>>();
    k_select1 <<<1, 1024>>>();
    k_hist2   <<<391, 256>>>();
    k_select2 <<<1, 1024>>>();
    k_mark_keep<<<1, 1024>>>();
    k_final   <<<(NNZ_C + 255) / 256, 256>>>(V_idx, E_idx, out);
}

// round 3
// speedup vs baseline: 3.0543x; 3.0543x over previous
#include <cuda_runtime.h>
#include <cstdint>

#define NNZ_C   1600000
#define NE_C    100000
#define KTOP_C  50000
#define D_C     128
#define H_C     32
#define NT_C    98          // ceil(NE_C / 1024)

// ---------------- device scratch (no allocations allowed) ----------------
__device__ int            g_counts[NE_C];
__device__ int            g_offsets[NE_C + 1];
__device__ int            g_cursor[NE_C];
__device__ int            g_csr_v[NNZ_C];
__device__ unsigned       g_keys[NE_C];
__device__ unsigned       g_hist1[65536];
__device__ unsigned       g_hist2[65536];
__device__ unsigned       g_coarse1[256];
__device__ unsigned       g_coarse2[256];
__device__ int            g_tile[NT_C];
__device__ int            g_tileb[NT_C];
__device__ unsigned       g_selHi;
__device__ unsigned       g_remK;
__device__ unsigned       g_thresh;
__device__ unsigned       g_rneed;
__device__ unsigned char  g_keep[NE_C];

// ---------------- init: zero the per-launch state ----------------
__global__ void __launch_bounds__(256) k_init() {
    int i = blockIdx.x * blockDim.x + threadIdx.x;
    int stride = gridDim.x * blockDim.x;
    for (int j = i; j < NE_C; j += stride) g_counts[j] = 0;
    for (int j = i; j < 65536; j += stride) { g_hist1[j] = 0; g_hist2[j] = 0; }
    if (i < 256) { g_coarse1[i] = 0; g_coarse2[i] = 0; }
}

// ---------------- pass A: degree counts ----------------
__global__ void __launch_bounds__(256) k_count(const int* __restrict__ E_idx) {
    int i0 = blockIdx.x * blockDim.x + threadIdx.x;
    int stride = gridDim.x * blockDim.x;
    for (int i = i0; i < NNZ_C; i += stride)
        atomicAdd(&g_counts[E_idx[i]], 1);
}

// ---------------- multi-block exclusive scan of counts ----------------
__global__ void __launch_bounds__(1024) k_scan_a() {
    __shared__ int wsum[32];
    int b = blockIdx.x, t = threadIdx.x;
    int lane = t & 31, w = t >> 5;
    int idx = b * 1024 + t;
    int c = (idx < NE_C) ? g_counts[idx] : 0;
    int v = c;
    #pragma unroll
    for (int o = 1; o < 32; o <<= 1) {
        int u = __shfl_up_sync(0xffffffffu, v, o);
        if (lane >= o) v += u;
    }
    if (lane == 31) wsum[w] = v;
    __syncthreads();
    if (w == 0) {
        int s = wsum[lane];
        #pragma unroll
        for (int o = 1; o < 32; o <<= 1) {
            int u = __shfl_up_sync(0xffffffffu, s, o);
            if (lane >= o) s += u;
        }
        wsum[lane] = s;
    }
    __syncthreads();
    int base = (w > 0) ? wsum[w - 1] : 0;
    int inc = v + base;
    if (idx < NE_C) g_offsets[idx] = inc - c;   // block-local exclusive
    if (t == 1023) g_tile[b] = inc;             // block total
}

__global__ void __launch_bounds__(128) k_scan_b() {
    __shared__ int s[128];
    int t = threadIdx.x;
    int v = (t < NT_C) ? g_tile[t] : 0;
    s[t] = v;
    __syncthreads();
    #pragma unroll
    for (int o = 1; o < 128; o <<= 1) {
        int u = (t >= o) ? s[t - o] : 0;
        __syncthreads();
        s[t] += u;
        __syncthreads();
    }
    if (t < NT_C) g_tileb[t] = s[t] - v;        // exclusive
}

__global__ void __launch_bounds__(1024) k_scan_c() {
    int b = blockIdx.x, t = threadIdx.x;
    int idx = b * 1024 + t;
    if (idx < NE_C) {
        int off = g_offsets[idx] + g_tileb[b];
        g_offsets[idx] = off;
        g_cursor[idx]  = off;                   // cursor starts at base offset
    }
    if (idx == 0) g_offsets[NE_C] = NNZ_C;
}

// ---------------- scatter V_idx into CSR order ----------------
__global__ void __launch_bounds__(256) k_scatter(const int* __restrict__ V_idx,
                                                 const int* __restrict__ E_idx) {
    int i0 = blockIdx.x * blockDim.x + threadIdx.x;
    int stride = gridDim.x * blockDim.x;
    for (int i = i0; i < NNZ_C; i += stride) {
        int e = E_idx[i];
        int p = atomicAdd(&g_cursor[e], 1);
        g_csr_v[p] = V_idx[i];
    }
}

// ---------------- fused edge-feature mean + MLP + sigmoid + hist1 ----------------
__global__ void __launch_bounds__(256) k_edge(
    const float* __restrict__ X,
    const float* __restrict__ W1,
    const float* __restrict__ b1,
    const float* __restrict__ W2,
    const float* __restrict__ b2,
    float* __restrict__ probs_out)
{
    __shared__ float  sW1[D_C * H_C];     // 16 KB, [d*32 + j]
    __shared__ float  sb1[H_C];
    __shared__ float  sW2[H_C];
    __shared__ float  sB2;
    __shared__ float4 sfeat[8][32];       // 4 KB

    int tid = threadIdx.x;
    for (int i = tid; i < D_C * H_C; i += blockDim.x) sW1[i] = W1[i];
    if (tid < H_C) { sb1[tid] = b1[tid]; sW2[tid] = W2[tid]; }
    if (tid == 0) sB2 = b2[0];
    __syncthreads();

    int warp = tid >> 5;
    int lane = tid & 31;

    for (int e = blockIdx.x * 8 + warp; e < NE_C; e += gridDim.x * 8) {
        int s   = g_offsets[e];
        int deg = g_offsets[e + 1] - s;

        float4 acc = make_float4(0.f, 0.f, 0.f, 0.f);
        for (int base = 0; base < deg; base += 32) {
            int n = min(32, deg - base);
            int v = (lane < n) ? g_csr_v[s + base + lane] : 0;
            #pragma unroll 4
            for (int m = 0; m < n; m++) {
                int vm = __shfl_sync(0xffffffffu, v, m);
                float4 x = __ldg(((const float4*)(X + (size_t)vm * D_C)) + lane);
                acc.x += x.x; acc.y += x.y; acc.z += x.z; acc.w += x.w;
            }
        }
        float inv = (deg > 0) ? (1.0f / (float)deg) : 0.0f;
        acc.x *= inv; acc.y *= inv; acc.z *= inv; acc.w *= inv;

        sfeat[warp][lane] = acc;
        __syncwarp();

        const float4* f4 = sfeat[warp];
        float h = sb1[lane];
        #pragma unroll
        for (int d4 = 0; d4 < 32; d4++) {
            float4 fv = f4[d4];
            h += fv.x * sW1[(d4 * 4 + 0) * H_C + lane];
            h += fv.y * sW1[(d4 * 4 + 1) * H_C + lane];
            h += fv.z * sW1[(d4 * 4 + 2) * H_C + lane];
            h += fv.w * sW1[(d4 * 4 + 3) * H_C + lane];
        }
        float contrib = fmaxf(h, 0.0f) * sW2[lane];
        #pragma unroll
        for (int off = 16; off > 0; off >>= 1)
            contrib += __shfl_xor_sync(0xffffffffu, contrib, off);

        if (lane == 0) {
            float logit = contrib + sB2;
            float prob  = 1.0f / (1.0f + expf(-logit));
            probs_out[e] = prob;
            unsigned key = __float_as_uint(prob);
            g_keys[e] = key;
            atomicAdd(&g_hist1[key >> 16], 1u);
            atomicAdd(&g_coarse1[key >> 24], 1u);
        }
        __syncwarp();
    }
}

// ---------------- select pass 1: coarse(256) + fine(256) scan in smem ----------------
__global__ void __launch_bounds__(256) k_select1() {
    __shared__ unsigned s[256];
    __shared__ unsigned sC, sK;
    int t = threadIdx.x;
    // coarse, descending bins: thread t <-> bin 255-t
    unsigned c = g_coarse1[255 - t];
    s[t] = c;
    __syncthreads();
    #pragma unroll
    for (int o = 1; o < 256; o <<= 1) {
        unsigned u = (t >= o) ? s[t - o] : 0;
        __syncthreads();
        s[t] += u;
        __syncthreads();
    }
    unsigned pre = (t > 0) ? s[t - 1] : 0;
    if (pre < KTOP_C && KTOP_C <= pre + c) { sC = 255 - t; sK = KTOP_C - pre; }
    __syncthreads();
    unsigned cb = sC, K2 = sK;
    // fine within coarse bin cb
    unsigned f = g_hist1[cb * 256 + (255 - t)];
    s[t] = f;
    __syncthreads();
    #pragma unroll
    for (int o = 1; o < 256; o <<= 1) {
        unsigned u = (t >= o) ? s[t - o] : 0;
        __syncthreads();
        s[t] += u;
        __syncthreads();
    }
    pre = (t > 0) ? s[t - 1] : 0;
    if (pre < K2 && K2 <= pre + f) {
        g_selHi = cb * 256 + (255 - t);
        g_remK  = K2 - pre;
    }
}

// ---------------- hist pass 2 (low 16 bits of matching keys) ----------------
__global__ void __launch_bounds__(256) k_hist2() {
    int i0 = blockIdx.x * blockDim.x + threadIdx.x;
    int stride = gridDim.x * blockDim.x;
    unsigned hi = g_selHi;
    for (int i = i0; i < NE_C; i += stride) {
        unsigned k = g_keys[i];
        if ((k >> 16) == hi) {
            atomicAdd(&g_hist2[k & 0xffffu], 1u);
            atomicAdd(&g_coarse2[(k >> 8) & 0xffu], 1u);
        }
    }
}

__global__ void __launch_bounds__(256) k_select2() {
    __shared__ unsigned s[256];
    __shared__ unsigned sC, sK;
    int t = threadIdx.x;
    unsigned K = g_remK;
    unsigned c = g_coarse2[255 - t];
    s[t] = c;
    __syncthreads();
    #pragma unroll
    for (int o = 1; o < 256; o <<= 1) {
        unsigned u = (t >= o) ? s[t - o] : 0;
        __syncthreads();
        s[t] += u;
        __syncthreads();
    }
    unsigned pre = (t > 0) ? s[t - 1] : 0;
    if (pre < K && K <= pre + c) { sC = 255 - t; sK = K - pre; }
    __syncthreads();
    unsigned cb = sC, K2 = sK;
    unsigned f = g_hist2[cb * 256 + (255 - t)];
    s[t] = f;
    __syncthreads();
    #pragma unroll
    for (int o = 1; o < 256; o <<= 1) {
        unsigned u = (t >= o) ? s[t - o] : 0;
        __syncthreads();
        s[t] += u;
        __syncthreads();
    }
    pre = (t > 0) ? s[t - 1] : 0;
    if (pre < K2 && K2 <= pre + f) {
        g_thresh = (g_selHi << 16) | (cb * 256 + (255 - t));
        g_rneed  = K2 - pre;
    }
}

// ---------------- deterministic keep marking (3-phase, multi-block) ----------------
__global__ void __launch_bounds__(1024) k_keep_a() {
    __shared__ int wsum[32];
    int b = blockIdx.x, t = threadIdx.x;
    int lane = t & 31, w = t >> 5;
    int idx = b * 1024 + t;
    unsigned T = g_thresh;
    int eq = (idx < NE_C && g_keys[idx] == T) ? 1 : 0;
    unsigned bal = __ballot_sync(0xffffffffu, eq);
    if (lane == 0) wsum[w] = __popc(bal);
    __syncthreads();
    if (t == 0) {
        int s = 0;
        #pragma unroll
        for (int i = 0; i < 32; i++) s += wsum[i];
        g_tile[b] = s;
    }
}

__global__ void __launch_bounds__(128) k_keep_b() {
    __shared__ int s[128];
    int t = threadIdx.x;
    int v = (t < NT_C) ? g_tile[t] : 0;
    s[t] = v;
    __syncthreads();
    #pragma unroll
    for (int o = 1; o < 128; o <<= 1) {
        int u = (t >= o) ? s[t - o] : 0;
        __syncthreads();
        s[t] += u;
        __syncthreads();
    }
    if (t < NT_C) g_tileb[t] = s[t] - v;
}

__global__ void __launch_bounds__(1024) k_keep_c() {
    __shared__ int wsum[32];
    int b = blockIdx.x, t = threadIdx.x;
    int lane = t & 31, w = t >> 5;
    int idx = b * 1024 + t;
    unsigned T = g_thresh;
    unsigned r = g_rneed;
    unsigned k = (idx < NE_C) ? g_keys[idx] : 0u;
    int eq = (idx < NE_C && k == T) ? 1 : 0;
    unsigned bal = __ballot_sync(0xffffffffu, eq);
    int pre = __popc(bal & ((1u << lane) - 1u));
    if (lane == 0) wsum[w] = __popc(bal);
    __syncthreads();
    if (w == 0) {
        int s = wsum[lane];
        #pragma unroll
        for (int o = 1; o < 32; o <<= 1) {
            int u = __shfl_up_sync(0xffffffffu, s, o);
            if (lane >= o) s += u;
        }
        wsum[lane] = s;
    }
    __syncthreads();
    int wbase = (w > 0) ? wsum[w - 1] : 0;
    if (idx < NE_C) {
        int rank = g_tileb[b] + wbase + pre;     // index-order rank among equals
        unsigned char kp;
        if (k > T)      kp = 1;
        else if (eq)    kp = (rank < (int)r) ? 1 : 0;
        else            kp = 0;
        g_keep[idx] = kp;
    }
}

// ---------------- final output (vectorized) ----------------
__global__ void __launch_bounds__(256) k_final(const int* __restrict__ V_idx,
                                               const int* __restrict__ E_idx,
                                               float* __restrict__ out)
{
    int i4 = blockIdx.x * blockDim.x + threadIdx.x;
    if (i4 >= NNZ_C / 4) return;
    int4 v = ((const int4*)V_idx)[i4];
    int4 e = ((const int4*)E_idx)[i4];
    bool m0 = g_keep[e.x] != 0;
    bool m1 = g_keep[e.y] != 0;
    bool m2 = g_keep[e.z] != 0;
    bool m3 = g_keep[e.w] != 0;
    float4 a, bb, mm;
    a.x = m0 ? (float)v.x : -1.0f;  bb.x = m0 ? (float)e.x : -1.0f;  mm.x = m0 ? 1.0f : 0.0f;
    a.y = m1 ? (float)v.y : -1.0f;  bb.y = m1 ? (float)e.y : -1.0f;  mm.y = m1 ? 1.0f : 0.0f;
    a.z = m2 ? (float)v.z : -1.0f;  bb.z = m2 ? (float)e.z : -1.0f;  mm.z = m2 ? 1.0f : 0.0f;
    a.w = m3 ? (float)v.w : -1.0f;  bb.w = m3 ? (float)e.w : -1.0f;  mm.w = m3 ? 1.0f : 0.0f;
    ((float4*)out)[i4]                           = a;
    ((float4*)(out + NNZ_C))[i4]                 = bb;
    ((float4*)(out + 2 * NNZ_C + NE_C))[i4]      = mm;
}

// ---------------- launch ----------------
extern "C" void kernel_launch(void* const* d_in, const int* in_sizes, int n_in,
                              void* d_out, int out_size)
{
    const float* X     = (const float*)d_in[0];
    const int*   V_idx = (const int*)  d_in[1];
    const int*   E_idx = (const int*)  d_in[2];
    const float* W1    = (const float*)d_in[3];
    const float* b1    = (const float*)d_in[4];
    const float* W2    = (const float*)d_in[5];
    const float* b2    = (const float*)d_in[6];
    float* out = (float*)d_out;
    float* probs_out = out + 2 * NNZ_C;

    k_init    <<<256, 256>>>();
    k_count   <<<1024, 256>>>(E_idx);
    k_scan_a  <<<NT_C, 1024>>>();
    k_scan_b  <<<1, 128>>>();
    k_scan_c  <<<NT_C, 1024>>>();
    k_scatter <<<1024, 256>>>(V_idx, E_idx);
    k_edge    <<<1184, 256>>>(X, W1, b1, W2, b2, probs_out);
    k_select1 <<<1, 256>>>();
    k_hist2   <<<391, 256>>>();
    k_select2 <<<1, 256>>>();
    k_keep_a  <<<NT_C, 1024>>>();
    k_keep_b  <<<1, 128>>>();
    k_keep_c  <<<NT_C, 1024>>>();
    k_final   <<<(NNZ_C / 4 + 255) / 256, 256>>>(V_idx, E_idx, out);
}

// round 4
// speedup vs baseline: 3.3855x; 1.1084x over previous
#include <cuda_runtime.h>
#include <cstdint>

#define NNZ_C   1600000
#define NE_C    100000
#define KTOP_C  50000
#define D_C     128
#define H_C     32
#define MAXDEG  128
#define NT_C    98          // ceil(NE_C / 1024)

// ---------------- device scratch (no allocations allowed) ----------------
__device__ int            g_cursor[NE_C];
__device__ int            g_bucket[(size_t)NE_C * MAXDEG];   // 51.2 MB
__device__ unsigned       g_keys[NE_C];
__device__ unsigned       g_hist1[65536];
__device__ unsigned       g_hist2[65536];
__device__ unsigned       g_coarse1[256];
__device__ unsigned       g_coarse2[256];
__device__ int            g_tile[NT_C];
__device__ int            g_tileb[NT_C];
__device__ unsigned       g_selHi;
__device__ unsigned       g_remK;
__device__ unsigned       g_thresh;
__device__ unsigned       g_rneed;
__device__ unsigned char  g_keep[NE_C];

// ---------------- init: zero per-launch state ----------------
__global__ void __launch_bounds__(256) k_init() {
    int i = blockIdx.x * blockDim.x + threadIdx.x;
    int stride = gridDim.x * blockDim.x;
    for (int j = i; j < NE_C; j += stride) g_cursor[j] = 0;
    for (int j = i; j < 65536; j += stride) { g_hist1[j] = 0; g_hist2[j] = 0; }
    if (i < 256) { g_coarse1[i] = 0; g_coarse2[i] = 0; }
}

// ---------------- direct bucket scatter (no count/scan needed) ----------------
__global__ void __launch_bounds__(256) k_scatter(const int* __restrict__ V_idx,
                                                 const int* __restrict__ E_idx) {
    int i0 = blockIdx.x * blockDim.x + threadIdx.x;
    int stride = gridDim.x * blockDim.x;
    for (int i4 = i0; i4 < NNZ_C / 4; i4 += stride) {
        int4 v = ((const int4*)V_idx)[i4];
        int4 e = ((const int4*)E_idx)[i4];
        int p0 = atomicAdd(&g_cursor[e.x], 1);
        g_bucket[(size_t)e.x * MAXDEG + p0] = v.x;
        int p1 = atomicAdd(&g_cursor[e.y], 1);
        g_bucket[(size_t)e.y * MAXDEG + p1] = v.y;
        int p2 = atomicAdd(&g_cursor[e.z], 1);
        g_bucket[(size_t)e.z * MAXDEG + p2] = v.z;
        int p3 = atomicAdd(&g_cursor[e.w], 1);
        g_bucket[(size_t)e.w * MAXDEG + p3] = v.w;
    }
}

// ---------------- fused edge-feature mean + MLP + sigmoid + hist1 ----------------
// One warp per edge. Lane l accumulates features [4l..4l+3] in a float4.
__global__ void __launch_bounds__(256) k_edge(
    const float* __restrict__ X,
    const float* __restrict__ W1,
    const float* __restrict__ b1,
    const float* __restrict__ W2,
    const float* __restrict__ b2,
    float* __restrict__ probs_out)
{
    __shared__ float  sW1[D_C * H_C];     // 16 KB, [d*32 + j]
    __shared__ float  sb1[H_C];
    __shared__ float  sW2[H_C];
    __shared__ float  sB2;
    __shared__ float4 sfeat[8][32];       // 4 KB

    int tid = threadIdx.x;
    for (int i = tid; i < D_C * H_C; i += blockDim.x) sW1[i] = W1[i];
    if (tid < H_C) { sb1[tid] = b1[tid]; sW2[tid] = W2[tid]; }
    if (tid == 0) sB2 = b2[0];
    __syncthreads();

    int warp = tid >> 5;
    int lane = tid & 31;

    for (int e = blockIdx.x * 8 + warp; e < NE_C; e += gridDim.x * 8) {
        int deg = g_cursor[e];
        const int* bkt = g_bucket + (size_t)e * MAXDEG;

        float4 acc = make_float4(0.f, 0.f, 0.f, 0.f);
        for (int base = 0; base < deg; base += 32) {
            int n = min(32, deg - base);
            int v = (lane < n) ? bkt[base + lane] : 0;
            #pragma unroll 4
            for (int m = 0; m < n; m++) {
                int vm = __shfl_sync(0xffffffffu, v, m);
                float4 x = __ldg(((const float4*)(X + (size_t)vm * D_C)) + lane);
                acc.x += x.x; acc.y += x.y; acc.z += x.z; acc.w += x.w;
            }
        }
        float inv = (deg > 0) ? (1.0f / (float)deg) : 0.0f;
        acc.x *= inv; acc.y *= inv; acc.z *= inv; acc.w *= inv;

        sfeat[warp][lane] = acc;
        __syncwarp();

        const float4* f4 = sfeat[warp];
        float h = sb1[lane];
        #pragma unroll
        for (int d4 = 0; d4 < 32; d4++) {
            float4 fv = f4[d4];
            h += fv.x * sW1[(d4 * 4 + 0) * H_C + lane];
            h += fv.y * sW1[(d4 * 4 + 1) * H_C + lane];
            h += fv.z * sW1[(d4 * 4 + 2) * H_C + lane];
            h += fv.w * sW1[(d4 * 4 + 3) * H_C + lane];
        }
        float contrib = fmaxf(h, 0.0f) * sW2[lane];
        #pragma unroll
        for (int off = 16; off > 0; off >>= 1)
            contrib += __shfl_xor_sync(0xffffffffu, contrib, off);

        if (lane == 0) {
            float logit = contrib + sB2;
            float prob  = 1.0f / (1.0f + expf(-logit));
            probs_out[e] = prob;
            unsigned key = __float_as_uint(prob);
            g_keys[e] = key;
            atomicAdd(&g_hist1[key >> 16], 1u);
            atomicAdd(&g_coarse1[key >> 24], 1u);
        }
        __syncwarp();
    }
}

// ---------------- select pass 1: coarse(256) + fine(256) scan in smem ----------------
__global__ void __launch_bounds__(256) k_select1() {
    __shared__ unsigned s[256];
    __shared__ unsigned sC, sK;
    int t = threadIdx.x;
    unsigned c = g_coarse1[255 - t];
    s[t] = c;
    __syncthreads();
    #pragma unroll
    for (int o = 1; o < 256; o <<= 1) {
        unsigned u = (t >= o) ? s[t - o] : 0;
        __syncthreads();
        s[t] += u;
        __syncthreads();
    }
    unsigned pre = (t > 0) ? s[t - 1] : 0;
    if (pre < KTOP_C && KTOP_C <= pre + c) { sC = 255 - t; sK = KTOP_C - pre; }
    __syncthreads();
    unsigned cb = sC, K2 = sK;
    unsigned f = g_hist1[cb * 256 + (255 - t)];
    s[t] = f;
    __syncthreads();
    #pragma unroll
    for (int o = 1; o < 256; o <<= 1) {
        unsigned u = (t >= o) ? s[t - o] : 0;
        __syncthreads();
        s[t] += u;
        __syncthreads();
    }
    pre = (t > 0) ? s[t - 1] : 0;
    if (pre < K2 && K2 <= pre + f) {
        g_selHi = cb * 256 + (255 - t);
        g_remK  = K2 - pre;
    }
}

// ---------------- hist pass 2 (low 16 bits of matching keys) ----------------
__global__ void __launch_bounds__(256) k_hist2() {
    int i0 = blockIdx.x * blockDim.x + threadIdx.x;
    int stride = gridDim.x * blockDim.x;
    unsigned hi = g_selHi;
    for (int i = i0; i < NE_C; i += stride) {
        unsigned k = g_keys[i];
        if ((k >> 16) == hi) {
            atomicAdd(&g_hist2[k & 0xffffu], 1u);
            atomicAdd(&g_coarse2[(k >> 8) & 0xffu], 1u);
        }
    }
}

__global__ void __launch_bounds__(256) k_select2() {
    __shared__ unsigned s[256];
    __shared__ unsigned sC, sK;
    int t = threadIdx.x;
    unsigned K = g_remK;
    unsigned c = g_coarse2[255 - t];
    s[t] = c;
    __syncthreads();
    #pragma unroll
    for (int o = 1; o < 256; o <<= 1) {
        unsigned u = (t >= o) ? s[t - o] : 0;
        __syncthreads();
        s[t] += u;
        __syncthreads();
    }
    unsigned pre = (t > 0) ? s[t - 1] : 0;
    if (pre < K && K <= pre + c) { sC = 255 - t; sK = K - pre; }
    __syncthreads();
    unsigned cb = sC, K2 = sK;
    unsigned f = g_hist2[cb * 256 + (255 - t)];
    s[t] = f;
    __syncthreads();
    #pragma unroll
    for (int o = 1; o < 256; o <<= 1) {
        unsigned u = (t >= o) ? s[t - o] : 0;
        __syncthreads();
        s[t] += u;
        __syncthreads();
    }
    pre = (t > 0) ? s[t - 1] : 0;
    if (pre < K2 && K2 <= pre + f) {
        g_thresh = (g_selHi << 16) | (cb * 256 + (255 - t));
        g_rneed  = K2 - pre;
    }
}

// ---------------- deterministic keep marking (3-phase, multi-block) ----------------
__global__ void __launch_bounds__(1024) k_keep_a() {
    __shared__ int wsum[32];
    int b = blockIdx.x, t = threadIdx.x;
    int lane = t & 31, w = t >> 5;
    int idx = b * 1024 + t;
    unsigned T = g_thresh;
    int eq = (idx < NE_C && g_keys[idx] == T) ? 1 : 0;
    unsigned bal = __ballot_sync(0xffffffffu, eq);
    if (lane == 0) wsum[w] = __popc(bal);
    __syncthreads();
    if (t == 0) {
        int s = 0;
        #pragma unroll
        for (int i = 0; i < 32; i++) s += wsum[i];
        g_tile[b] = s;
    }
}

__global__ void __launch_bounds__(128) k_keep_b() {
    __shared__ int s[128];
    int t = threadIdx.x;
    int v = (t < NT_C) ? g_tile[t] : 0;
    s[t] = v;
    __syncthreads();
    #pragma unroll
    for (int o = 1; o < 128; o <<= 1) {
        int u = (t >= o) ? s[t - o] : 0;
        __syncthreads();
        s[t] += u;
        __syncthreads();
    }
    if (t < NT_C) g_tileb[t] = s[t] - v;
}

__global__ void __launch_bounds__(1024) k_keep_c() {
    __shared__ int wsum[32];
    int b = blockIdx.x, t = threadIdx.x;
    int lane = t & 31, w = t >> 5;
    int idx = b * 1024 + t;
    unsigned T = g_thresh;
    unsigned r = g_rneed;
    unsigned k = (idx < NE_C) ? g_keys[idx] : 0u;
    int eq = (idx < NE_C && k == T) ? 1 : 0;
    unsigned bal = __ballot_sync(0xffffffffu, eq);
    int pre = __popc(bal & ((1u << lane) - 1u));
    if (lane == 0) wsum[w] = __popc(bal);
    __syncthreads();
    if (w == 0) {
        int s = wsum[lane];
        #pragma unroll
        for (int o = 1; o < 32; o <<= 1) {
            int u = __shfl_up_sync(0xffffffffu, s, o);
            if (lane >= o) s += u;
        }
        wsum[lane] = s;
    }
    __syncthreads();
    int wbase = (w > 0) ? wsum[w - 1] : 0;
    if (idx < NE_C) {
        int rank = g_tileb[b] + wbase + pre;     // index-order rank among equals
        unsigned char kp;
        if (k > T)      kp = 1;
        else if (eq)    kp = (rank < (int)r) ? 1 : 0;
        else            kp = 0;
        g_keep[idx] = kp;
    }
}

// ---------------- final output (vectorized, streaming stores) ----------------
__global__ void __launch_bounds__(256) k_final(const int* __restrict__ V_idx,
                                               const int* __restrict__ E_idx,
                                               float* __restrict__ out)
{
    int i4 = blockIdx.x * blockDim.x + threadIdx.x;
    if (i4 >= NNZ_C / 4) return;
    int4 v = ((const int4*)V_idx)[i4];
    int4 e = ((const int4*)E_idx)[i4];
    bool m0 = g_keep[e.x] != 0;
    bool m1 = g_keep[e.y] != 0;
    bool m2 = g_keep[e.z] != 0;
    bool m3 = g_keep[e.w] != 0;
    float4 a, bb, mm;
    a.x = m0 ? (float)v.x : -1.0f;  bb.x = m0 ? (float)e.x : -1.0f;  mm.x = m0 ? 1.0f : 0.0f;
    a.y = m1 ? (float)v.y : -1.0f;  bb.y = m1 ? (float)e.y : -1.0f;  mm.y = m1 ? 1.0f : 0.0f;
    a.z = m2 ? (float)v.z : -1.0f;  bb.z = m2 ? (float)e.z : -1.0f;  mm.z = m2 ? 1.0f : 0.0f;
    a.w = m3 ? (float)v.w : -1.0f;  bb.w = m3 ? (float)e.w : -1.0f;  mm.w = m3 ? 1.0f : 0.0f;
    __stcs(((float4*)out) + i4, a);
    __stcs(((float4*)(out + NNZ_C)) + i4, bb);
    __stcs(((float4*)(out + 2 * NNZ_C + NE_C)) + i4, mm);
}

// ---------------- launch ----------------
extern "C" void kernel_launch(void* const* d_in, const int* in_sizes, int n_in,
                              void* d_out, int out_size)
{
    const float* X     = (const float*)d_in[0];
    const int*   V_idx = (const int*)  d_in[1];
    const int*   E_idx = (const int*)  d_in[2];
    const float* W1    = (const float*)d_in[3];
    const float* b1    = (const float*)d_in[4];
    const float* W2    = (const float*)d_in[5];
    const float* b2    = (const float*)d_in[6];
    float* out = (float*)d_out;
    float* probs_out = out + 2 * NNZ_C;

    k_init    <<<256, 256>>>();
    k_scatter <<<1024, 256>>>(V_idx, E_idx);
    k_edge    <<<1184, 256>>>(X, W1, b1, W2, b2, probs_out);
    k_select1 <<<1, 256>>>();
    k_hist2   <<<391, 256>>>();
    k_select2 <<<1, 256>>>();
    k_keep_a  <<<NT_C, 1024>>>();
    k_keep_b  <<<1, 128>>>();
    k_keep_c  <<<NT_C, 1024>>>();
    k_final   <<<(NNZ_C / 4 + 255) / 256, 256>>>(V_idx, E_idx, out);
}